// round 1
// baseline (speedup 1.0000x reference)
#include <cuda_runtime.h>

// Problem constants
#define NWIN   4096
#define NTOK   49
#define CDIM   384
#define HEADS  12
#define HDIM   32
#define MROWS  (NWIN * NTOK)        // 200704
#define QKVCOL (3 * CDIM)           // 1152

// Scratch (allocation-free rule: __device__ globals)
__device__ float g_qkv[(size_t)MROWS * QKVCOL];  // 231,211,008 floats (~924 MB)
__device__ float g_att[(size_t)MROWS * CDIM];    //  77,070,336 floats (~308 MB)

// ---------------------------------------------------------------------------
// SGEMM: C[M,N] = A[M,K] @ B[K,N] + bias[N]
// 128x128 block tile, BK=8, 8x8 per thread, double-buffered smem.
// Requires M%128==0, N%128==0, K%8==0 (true for all our shapes).
// ---------------------------------------------------------------------------
__global__ __launch_bounds__(256) void sgemm_bias(
    const float* __restrict__ A, const float* __restrict__ B,
    const float* __restrict__ bias, float* __restrict__ C,
    int M, int N, int K)
{
    const int BM = 128, BN = 128, BK = 8;
    __shared__ float As[2][BK][BM];
    __shared__ float Bs[2][BK][BN];

    const int tid = threadIdx.x;
    const int tx  = tid & 15;   // 0..15
    const int ty  = tid >> 4;   // 0..15
    const int blockM = blockIdx.y * BM;
    const int blockN = blockIdx.x * BN;

    // A-tile load mapping: 128x8 = 256 float4
    const int aRow = tid >> 1;        // 0..127
    const int aCol = (tid & 1) * 4;   // 0 or 4
    // B-tile load mapping: 8x128 = 256 float4
    const int bRow = tid >> 5;        // 0..7
    const int bCol = (tid & 31) * 4;  // 0..124

    const float* Aptr = A + (long long)(blockM + aRow) * K + aCol;
    const float* Bptr = B + (long long)bRow * N + blockN + bCol;

    float acc[8][8];
#pragma unroll
    for (int i = 0; i < 8; i++)
#pragma unroll
        for (int j = 0; j < 8; j++) acc[i][j] = 0.0f;

    const int nTiles = K / BK;

    // Prime buffer 0
    {
        float4 a4 = *(const float4*)(Aptr);
        float4 b4 = *(const float4*)(Bptr);
        As[0][aCol + 0][aRow] = a4.x;
        As[0][aCol + 1][aRow] = a4.y;
        As[0][aCol + 2][aRow] = a4.z;
        As[0][aCol + 3][aRow] = a4.w;
        *(float4*)&Bs[0][bRow][bCol] = b4;
    }
    __syncthreads();

    for (int t = 0; t < nTiles; t++) {
        const int cur = t & 1;
        float4 a4n, b4n;
        const bool hasNext = (t + 1 < nTiles);
        if (hasNext) {
            a4n = *(const float4*)(Aptr + (t + 1) * BK);
            b4n = *(const float4*)(Bptr + (long long)(t + 1) * BK * N);
        }
#pragma unroll
        for (int kk = 0; kk < BK; kk++) {
            float rm[8], rn[8];
            *(float4*)&rm[0] = *(float4*)&As[cur][kk][ty * 8];
            *(float4*)&rm[4] = *(float4*)&As[cur][kk][ty * 8 + 4];
            *(float4*)&rn[0] = *(float4*)&Bs[cur][kk][tx * 8];
            *(float4*)&rn[4] = *(float4*)&Bs[cur][kk][tx * 8 + 4];
#pragma unroll
            for (int i = 0; i < 8; i++)
#pragma unroll
                for (int j = 0; j < 8; j++)
                    acc[i][j] = fmaf(rm[i], rn[j], acc[i][j]);
        }
        if (hasNext) {
            const int nxt = cur ^ 1;
            As[nxt][aCol + 0][aRow] = a4n.x;
            As[nxt][aCol + 1][aRow] = a4n.y;
            As[nxt][aCol + 2][aRow] = a4n.z;
            As[nxt][aCol + 3][aRow] = a4n.w;
            *(float4*)&Bs[nxt][bRow][bCol] = b4n;
            __syncthreads();
        }
    }

    // Epilogue: bias + store
    float bv[8];
#pragma unroll
    for (int j = 0; j < 8; j++) bv[j] = bias[blockN + tx * 8 + j];

#pragma unroll
    for (int i = 0; i < 8; i++) {
        const long long row = blockM + ty * 8 + i;
        const int col = blockN + tx * 8;
        float4 v0, v1;
        v0.x = acc[i][0] + bv[0];
        v0.y = acc[i][1] + bv[1];
        v0.z = acc[i][2] + bv[2];
        v0.w = acc[i][3] + bv[3];
        v1.x = acc[i][4] + bv[4];
        v1.y = acc[i][5] + bv[5];
        v1.z = acc[i][6] + bv[6];
        v1.w = acc[i][7] + bv[7];
        *(float4*)&C[row * N + col]     = v0;
        *(float4*)&C[row * N + col + 4] = v1;
    }
}

// ---------------------------------------------------------------------------
// Fused window attention: one block per (window, head).
// Loads q,k,v (49x32 each) to smem, computes S = scale*q@k^T + rel_bias,
// row softmax, O = P@v, writes (B,N,C) with C = h*32 + d.
// ---------------------------------------------------------------------------
__global__ __launch_bounds__(256) void attn_kernel(
    const float* __restrict__ qkv,
    const float* __restrict__ bias_table,
    float* __restrict__ out)
{
    __shared__ float qs[NTOK][HDIM + 1];
    __shared__ float ks[NTOK][HDIM + 1];
    __shared__ float vs[NTOK][HDIM + 1];
    __shared__ float S[NTOK][NTOK + 3];

    const int b   = blockIdx.x;
    const int h   = blockIdx.y;
    const int tid = threadIdx.x;
    const float scale = 0.17677669529663687f;  // 32^-0.5

    // Stage q,k,v
    for (int idx = tid; idx < NTOK * HDIM; idx += 256) {
        const int n = idx >> 5, d = idx & 31;
        const size_t base = ((size_t)(b * NTOK + n)) * QKVCOL + h * HDIM + d;
        qs[n][d] = qkv[base] * scale;
        ks[n][d] = qkv[base + CDIM];
        vs[n][d] = qkv[base + 2 * CDIM];
    }
    __syncthreads();

    // Scores + relative position bias
    for (int idx = tid; idx < NTOK * NTOK; idx += 256) {
        const int i = idx / NTOK;
        const int j = idx - i * NTOK;
        const int ri = i / 7, ci = i - ri * 7;
        const int rj = j / 7, cj = j - rj * 7;
        const int relidx = (ri - rj + 6) * 13 + (ci - cj + 6);
        float a = bias_table[relidx * HEADS + h];
#pragma unroll
        for (int d = 0; d < HDIM; d++) a = fmaf(qs[i][d], ks[j][d], a);
        S[i][j] = a;
    }
    __syncthreads();

    // Row softmax (one thread per row)
    if (tid < NTOK) {
        float m = -1e30f;
#pragma unroll 7
        for (int j = 0; j < NTOK; j++) m = fmaxf(m, S[tid][j]);
        float s = 0.0f;
#pragma unroll 7
        for (int j = 0; j < NTOK; j++) {
            const float e = __expf(S[tid][j] - m);
            S[tid][j] = e;
            s += e;
        }
        const float inv = 1.0f / s;
#pragma unroll 7
        for (int j = 0; j < NTOK; j++) S[tid][j] *= inv;
    }
    __syncthreads();

    // O = P @ V
    for (int idx = tid; idx < NTOK * HDIM; idx += 256) {
        const int i = idx >> 5, d = idx & 31;
        float a = 0.0f;
#pragma unroll 7
        for (int j = 0; j < NTOK; j++) a = fmaf(S[i][j], vs[j][d], a);
        out[((size_t)(b * NTOK + i)) * CDIM + h * HDIM + d] = a;
    }
}

// ---------------------------------------------------------------------------
extern "C" void kernel_launch(void* const* d_in, const int* in_sizes, int n_in,
                              void* d_out, int out_size)
{
    const float* x          = (const float*)d_in[0];
    const float* w_qkv      = (const float*)d_in[1];
    const float* b_qkv      = (const float*)d_in[2];
    const float* w_proj     = (const float*)d_in[3];
    const float* b_proj     = (const float*)d_in[4];
    const float* bias_table = (const float*)d_in[5];
    float* out = (float*)d_out;

    float *qkv, *att;
    cudaGetSymbolAddress((void**)&qkv, g_qkv);
    cudaGetSymbolAddress((void**)&att, g_att);

    // 1) QKV = x @ w_qkv + b_qkv   (200704 x 1152, K=384)
    {
        dim3 grid(QKVCOL / 128, MROWS / 128);  // (9, 1568)
        sgemm_bias<<<grid, 256>>>(x, w_qkv, b_qkv, qkv, MROWS, QKVCOL, CDIM);
    }
    // 2) Windowed attention
    {
        dim3 grid(NWIN, HEADS);  // (4096, 12)
        attn_kernel<<<grid, 256>>>(qkv, bias_table, att);
    }
    // 3) out = att @ w_proj + b_proj   (200704 x 384, K=384)
    {
        dim3 grid(CDIM / 128, MROWS / 128);  // (3, 1568)
        sgemm_bias<<<grid, 256>>>(att, w_proj, b_proj, out, MROWS, CDIM, CDIM);
    }
}

// round 3
// speedup vs baseline: 2.1730x; 2.1730x over previous
#include <cuda_runtime.h>
#include <float.h>

// Problem constants
#define NWIN   4096
#define NTOK   49
#define CDIM   384
#define HEADS  12
#define HDIM   32
#define MROWS  (NWIN * NTOK)        // 200704
#define QKVCOL (3 * CDIM)           // 1152

// Scratch (allocation-free rule: __device__ globals)
__device__ float g_qkv[(size_t)MROWS * QKVCOL];  // ~924 MB
__device__ float g_att[(size_t)MROWS * CDIM];    // ~308 MB

__device__ __forceinline__ unsigned f2tf32(float f) {
    unsigned u;
    asm("cvt.rna.tf32.f32 %0, %1;" : "=r"(u) : "f"(f));
    return u;
}

// ---------------------------------------------------------------------------
// TF32 tensor-core SGEMM: C[M,N] = A[M,K] @ B[K,N] + bias[N]
// 128x128 block, BK=16, 8 warps (4 in M x 2 in N), warp tile 32x64,
// mma.sync.m16n8k8 tf32, fp32 accumulate. Double-buffered smem.
// Requires M%128==0, N%128==0, K%16==0.
// ---------------------------------------------------------------------------
#define BM 128
#define BN 128
#define BK 16
#define LDS_A 136   // BM + 8 : conflict-free fragment loads
#define LDS_B 136   // BN + 8

__global__ __launch_bounds__(256) void gemm_tf32(
    const float* __restrict__ A, const float* __restrict__ B,
    const float* __restrict__ bias, float* __restrict__ C,
    int M, int N, int K)
{
    __shared__ unsigned As[2][BK][LDS_A];
    __shared__ unsigned Bs[2][BK][LDS_B];

    const int tid  = threadIdx.x;
    const int lane = tid & 31;
    const int warp = tid >> 5;
    const int warpM = warp & 3;     // 0..3
    const int warpN = warp >> 2;    // 0..1
    const int g = lane >> 2;        // groupID 0..7
    const int c = lane & 3;         // tid-in-group 0..3

    const int blockM = blockIdx.y * BM;
    const int blockN = blockIdx.x * BN;

    const int aRow0 = tid >> 2;          // 0..63
    const int aCol  = (tid & 3) * 4;     // 0,4,8,12
    const int bRow0 = tid >> 5;          // 0..7
    const int bCol  = (tid & 31) * 4;

    const float* Aptr0 = A + (long long)(blockM + aRow0) * K + aCol;
    const float* Aptr1 = A + (long long)(blockM + aRow0 + 64) * K + aCol;
    const float* Bptr0 = B + (long long)bRow0 * N + blockN + bCol;
    const float* Bptr1 = B + (long long)(bRow0 + 8) * N + blockN + bCol;

    float acc[2][8][4];
#pragma unroll
    for (int mt = 0; mt < 2; mt++)
#pragma unroll
        for (int nt = 0; nt < 8; nt++)
#pragma unroll
            for (int r = 0; r < 4; r++) acc[mt][nt][r] = 0.0f;

    const int nTiles = K / BK;

    // Prime buffer 0
    {
        float4 a0 = *(const float4*)(Aptr0);
        float4 a1 = *(const float4*)(Aptr1);
        float4 b0 = *(const float4*)(Bptr0);
        float4 b1 = *(const float4*)(Bptr1);
        As[0][aCol + 0][aRow0] = f2tf32(a0.x);
        As[0][aCol + 1][aRow0] = f2tf32(a0.y);
        As[0][aCol + 2][aRow0] = f2tf32(a0.z);
        As[0][aCol + 3][aRow0] = f2tf32(a0.w);
        As[0][aCol + 0][aRow0 + 64] = f2tf32(a1.x);
        As[0][aCol + 1][aRow0 + 64] = f2tf32(a1.y);
        As[0][aCol + 2][aRow0 + 64] = f2tf32(a1.z);
        As[0][aCol + 3][aRow0 + 64] = f2tf32(a1.w);
        uint4 u0 = { f2tf32(b0.x), f2tf32(b0.y), f2tf32(b0.z), f2tf32(b0.w) };
        uint4 u1 = { f2tf32(b1.x), f2tf32(b1.y), f2tf32(b1.z), f2tf32(b1.w) };
        *(uint4*)&Bs[0][bRow0][bCol]     = u0;
        *(uint4*)&Bs[0][bRow0 + 8][bCol] = u1;
    }
    __syncthreads();

    int buf = 0;
    for (int kt = 0; kt < nTiles; kt++) {
        const bool hasNext = (kt + 1 < nTiles);
        float4 pa0, pa1, pb0, pb1;
        if (hasNext) {
            pa0 = *(const float4*)(Aptr0 + (kt + 1) * BK);
            pa1 = *(const float4*)(Aptr1 + (kt + 1) * BK);
            pb0 = *(const float4*)(Bptr0 + (long long)(kt + 1) * BK * N);
            pb1 = *(const float4*)(Bptr1 + (long long)(kt + 1) * BK * N);
        }

        // Two k8 steps
#pragma unroll
        for (int ks = 0; ks < 2; ks++) {
            const int k0 = ks * 8;
            unsigned af[2][4];
#pragma unroll
            for (int mt = 0; mt < 2; mt++) {
                const int r = warpM * 32 + mt * 16;
                af[mt][0] = As[buf][k0 + c][r + g];
                af[mt][1] = As[buf][k0 + c][r + g + 8];
                af[mt][2] = As[buf][k0 + c + 4][r + g];
                af[mt][3] = As[buf][k0 + c + 4][r + g + 8];
            }
            unsigned bf[8][2];
#pragma unroll
            for (int nt = 0; nt < 8; nt++) {
                const int col = warpN * 64 + nt * 8;
                bf[nt][0] = Bs[buf][k0 + c][col + g];
                bf[nt][1] = Bs[buf][k0 + c + 4][col + g];
            }
#pragma unroll
            for (int mt = 0; mt < 2; mt++)
#pragma unroll
                for (int nt = 0; nt < 8; nt++) {
                    float* d = acc[mt][nt];
                    asm volatile(
                        "mma.sync.aligned.m16n8k8.row.col.f32.tf32.tf32.f32 "
                        "{%0,%1,%2,%3}, {%4,%5,%6,%7}, {%8,%9}, {%0,%1,%2,%3};\n"
                        : "+f"(d[0]), "+f"(d[1]), "+f"(d[2]), "+f"(d[3])
                        : "r"(af[mt][0]), "r"(af[mt][1]), "r"(af[mt][2]), "r"(af[mt][3]),
                          "r"(bf[nt][0]), "r"(bf[nt][1]));
                }
        }

        if (hasNext) {
            const int nxt = buf ^ 1;
            As[nxt][aCol + 0][aRow0] = f2tf32(pa0.x);
            As[nxt][aCol + 1][aRow0] = f2tf32(pa0.y);
            As[nxt][aCol + 2][aRow0] = f2tf32(pa0.z);
            As[nxt][aCol + 3][aRow0] = f2tf32(pa0.w);
            As[nxt][aCol + 0][aRow0 + 64] = f2tf32(pa1.x);
            As[nxt][aCol + 1][aRow0 + 64] = f2tf32(pa1.y);
            As[nxt][aCol + 2][aRow0 + 64] = f2tf32(pa1.z);
            As[nxt][aCol + 3][aRow0 + 64] = f2tf32(pa1.w);
            uint4 u0 = { f2tf32(pb0.x), f2tf32(pb0.y), f2tf32(pb0.z), f2tf32(pb0.w) };
            uint4 u1 = { f2tf32(pb1.x), f2tf32(pb1.y), f2tf32(pb1.z), f2tf32(pb1.w) };
            *(uint4*)&Bs[nxt][bRow0][bCol]     = u0;
            *(uint4*)&Bs[nxt][bRow0 + 8][bCol] = u1;
            __syncthreads();
            buf = nxt;
        }
    }

    // Epilogue: bias + store
#pragma unroll
    for (int nt = 0; nt < 8; nt++) {
        const int col = blockN + warpN * 64 + nt * 8 + 2 * c;
        const float bv0 = bias[col];
        const float bv1 = bias[col + 1];
#pragma unroll
        for (int mt = 0; mt < 2; mt++) {
            const long long row0 = blockM + warpM * 32 + mt * 16 + g;
            float2 v0 = { acc[mt][nt][0] + bv0, acc[mt][nt][1] + bv1 };
            float2 v1 = { acc[mt][nt][2] + bv0, acc[mt][nt][3] + bv1 };
            *(float2*)&C[row0 * N + col]       = v0;
            *(float2*)&C[(row0 + 8) * N + col] = v1;
        }
    }
}

// ---------------------------------------------------------------------------
// Fused window attention: block = (window, head), 128 threads (4 warps).
// Warp-per-row softmax fully in registers (shuffle reductions).
// ---------------------------------------------------------------------------
__global__ __launch_bounds__(128) void attn_kernel(
    const float* __restrict__ qkv,
    const float* __restrict__ bias_table,
    float* __restrict__ out)
{
    __shared__ float qs[NTOK][HDIM + 1];
    __shared__ float ks[NTOK][HDIM + 1];
    __shared__ float vs[NTOK][HDIM + 1];
    __shared__ float P[NTOK][NTOK + 3];
    __shared__ float bt[169];   // bias_table column for this head (13*13)

    const int b    = blockIdx.x;
    const int h    = blockIdx.y;
    const int tid  = threadIdx.x;
    const int lane = tid & 31;
    const int warp = tid >> 5;
    const float scale = 0.17677669529663687f;  // 32^-0.5

    // Stage bias column (FIX: strided loop — 128 threads must cover 169 entries)
    for (int idx = tid; idx < 169; idx += 128) bt[idx] = bias_table[idx * HEADS + h];
    // Stage q,k,v
    for (int idx = tid; idx < NTOK * HDIM; idx += 128) {
        const int n = idx >> 5, d = idx & 31;
        const size_t base = ((size_t)(b * NTOK + n)) * QKVCOL + h * HDIM + d;
        qs[n][d] = qkv[base] * scale;
        ks[n][d] = qkv[base + CDIM];
        vs[n][d] = qkv[base + 2 * CDIM];
    }
    __syncthreads();

    // Scores + softmax: warp per row, row j-cols split lane / lane+32
    const int j1 = lane + 32;
    const int rj0 = lane / 7,  cj0 = lane - rj0 * 7;
    const int rj1 = j1 / 7,    cj1 = j1 - rj1 * 7;
    for (int i = warp; i < NTOK; i += 4) {
        const int ri = i / 7, ci = i - ri * 7;
        float s0 = bt[(ri - rj0 + 6) * 13 + (ci - cj0 + 6)];
#pragma unroll
        for (int d = 0; d < HDIM; d++) s0 = fmaf(qs[i][d], ks[lane][d], s0);
        float s1 = -FLT_MAX;
        if (j1 < NTOK) {
            s1 = bt[(ri - rj1 + 6) * 13 + (ci - cj1 + 6)];
#pragma unroll
            for (int d = 0; d < HDIM; d++) s1 = fmaf(qs[i][d], ks[j1][d], s1);
        }
        float m = fmaxf(s0, s1);
#pragma unroll
        for (int off = 16; off >= 1; off >>= 1)
            m = fmaxf(m, __shfl_xor_sync(0xffffffffu, m, off));
        const float e0 = __expf(s0 - m);
        const float e1 = (j1 < NTOK) ? __expf(s1 - m) : 0.0f;
        float s = e0 + e1;
#pragma unroll
        for (int off = 16; off >= 1; off >>= 1)
            s += __shfl_xor_sync(0xffffffffu, s, off);
        const float inv = 1.0f / s;
        P[i][lane] = e0 * inv;
        if (j1 < NTOK) P[i][j1] = e1 * inv;
    }
    __syncthreads();

    // O = P @ V
    for (int idx = tid; idx < NTOK * HDIM; idx += 128) {
        const int i = idx >> 5, d = idx & 31;
        float a = 0.0f;
#pragma unroll 7
        for (int j = 0; j < NTOK; j++) a = fmaf(P[i][j], vs[j][d], a);
        out[((size_t)(b * NTOK + i)) * CDIM + h * HDIM + d] = a;
    }
}

// ---------------------------------------------------------------------------
extern "C" void kernel_launch(void* const* d_in, const int* in_sizes, int n_in,
                              void* d_out, int out_size)
{
    const float* x          = (const float*)d_in[0];
    const float* w_qkv      = (const float*)d_in[1];
    const float* b_qkv      = (const float*)d_in[2];
    const float* w_proj     = (const float*)d_in[3];
    const float* b_proj     = (const float*)d_in[4];
    const float* bias_table = (const float*)d_in[5];
    float* out = (float*)d_out;

    float *qkv, *att;
    cudaGetSymbolAddress((void**)&qkv, g_qkv);
    cudaGetSymbolAddress((void**)&att, g_att);

    // 1) QKV = x @ w_qkv + b_qkv   (200704 x 1152, K=384)
    {
        dim3 grid(QKVCOL / BN, MROWS / BM);  // (9, 1568)
        gemm_tf32<<<grid, 256>>>(x, w_qkv, b_qkv, qkv, MROWS, QKVCOL, CDIM);
    }
    // 2) Windowed attention
    {
        dim3 grid(NWIN, HEADS);  // (4096, 12)
        attn_kernel<<<grid, 128>>>(qkv, bias_table, att);
    }
    // 3) out = att @ w_proj + b_proj   (200704 x 384, K=384)
    {
        dim3 grid(CDIM / BN, MROWS / BM);  // (3, 1568)
        gemm_tf32<<<grid, 256>>>(att, w_proj, b_proj, out, MROWS, CDIM, CDIM);
    }
}

// round 4
// speedup vs baseline: 3.2518x; 1.4965x over previous
#include <cuda_runtime.h>
#include <cuda_fp16.h>
#include <float.h>

// Problem constants
#define NWIN   4096
#define NTOK   49
#define CDIM   384
#define HEADS  12
#define HDIM   32
#define MROWS  (NWIN * NTOK)        // 200704
#define QKVCOL (3 * CDIM)           // 1152

// Scratch (allocation-free rule: __device__ globals)
__device__ __half g_xh   [(size_t)MROWS * CDIM];     // 154 MB
__device__ __half g_wqkvh[(size_t)CDIM * QKVCOL];
__device__ __half g_wprojh[(size_t)CDIM * CDIM];
__device__ __half g_qkvh [(size_t)MROWS * QKVCOL];   // 462 MB
__device__ __half g_atth [(size_t)MROWS * CDIM];     // 154 MB

// ---------------------------------------------------------------------------
// fp32 -> fp16 conversion (vectorized)
// ---------------------------------------------------------------------------
__global__ void f32_to_f16(const float* __restrict__ in, __half* __restrict__ out, int n4)
{
    int i = blockIdx.x * blockDim.x + threadIdx.x;
    if (i < n4) {
        float4 v = ((const float4*)in)[i];
        __half2 h0 = __floats2half2_rn(v.x, v.y);
        __half2 h1 = __floats2half2_rn(v.z, v.w);
        ((__half2*)out)[2 * i]     = h0;
        ((__half2*)out)[2 * i + 1] = h1;
    }
}

// ---------------------------------------------------------------------------
// FP16 tensor-core GEMM: C[M,N] = A[M,K] @ B[K,N] + bias[N]
// 128x128 block, BK=32 halves, 8 warps (4M x 2N), warp tile 32x64.
// mma.sync.m16n8k16 f16->f32, ldmatrix fragment loads, cp.async staging.
// ---------------------------------------------------------------------------
#define BM 128
#define BN 128
#define BKH 32
#define SA 40    // A row stride in halves (80B: conflict-free ldmatrix)
#define SB 136   // B row stride in halves (272B: conflict-free ldmatrix)

__device__ __forceinline__ void ldsm_x4(unsigned& r0, unsigned& r1, unsigned& r2, unsigned& r3,
                                        const void* p) {
    unsigned a = (unsigned)__cvta_generic_to_shared(p);
    asm volatile("ldmatrix.sync.aligned.m8n8.x4.shared.b16 {%0,%1,%2,%3}, [%4];"
                 : "=r"(r0), "=r"(r1), "=r"(r2), "=r"(r3) : "r"(a));
}
__device__ __forceinline__ void ldsm_x4_t(unsigned& r0, unsigned& r1, unsigned& r2, unsigned& r3,
                                          const void* p) {
    unsigned a = (unsigned)__cvta_generic_to_shared(p);
    asm volatile("ldmatrix.sync.aligned.m8n8.x4.trans.shared.b16 {%0,%1,%2,%3}, [%4];"
                 : "=r"(r0), "=r"(r1), "=r"(r2), "=r"(r3) : "r"(a));
}
__device__ __forceinline__ void cp16(const void* smem_dst, const void* gmem_src) {
    unsigned d = (unsigned)__cvta_generic_to_shared(smem_dst);
    asm volatile("cp.async.cg.shared.global [%0], [%1], 16;" :: "r"(d), "l"(gmem_src));
}

template<bool OUT_HALF>
__global__ __launch_bounds__(256) void gemm_f16(
    const __half* __restrict__ A, const __half* __restrict__ B,
    const float* __restrict__ bias, void* __restrict__ Cout,
    int M, int N, int K)
{
    __shared__ __align__(16) __half As[2][BM][SA];
    __shared__ __align__(16) __half Bs[2][BKH][SB];

    const int tid  = threadIdx.x;
    const int lane = tid & 31;
    const int warp = tid >> 5;
    const int warpM = warp & 3;     // 0..3
    const int warpN = warp >> 2;    // 0..1
    const int g = lane >> 2;        // 0..7
    const int c = lane & 3;         // 0..3
    const int blockM = blockIdx.y * BM;
    const int blockN = blockIdx.x * BN;

    // cp.async mappings (16B chunks)
    const int aRow  = tid >> 2;         // 0..63 (+64 for 2nd chunk)
    const int aCol8 = (tid & 3) * 8;    // halves 0,8,16,24
    const int bRow  = tid >> 4;         // 0..15 (+16 for 2nd chunk)
    const int bCol8 = (tid & 15) * 8;   // halves 0..120

    const __half* Aptr0 = A + (long long)(blockM + aRow) * K + aCol8;
    const __half* Aptr1 = A + (long long)(blockM + aRow + 64) * K + aCol8;
    const __half* Bptr0 = B + (long long)bRow * N + blockN + bCol8;
    const __half* Bptr1 = B + (long long)(bRow + 16) * N + blockN + bCol8;

    float acc[2][8][4];
#pragma unroll
    for (int mt = 0; mt < 2; mt++)
#pragma unroll
        for (int nt = 0; nt < 8; nt++)
#pragma unroll
            for (int r = 0; r < 4; r++) acc[mt][nt][r] = 0.0f;

    const int nTiles = K / BKH;

#define LOAD_STAGE(bufi, kt)                                                       \
    do {                                                                           \
        cp16(&As[bufi][aRow][aCol8],      Aptr0 + (kt) * BKH);                     \
        cp16(&As[bufi][aRow + 64][aCol8], Aptr1 + (kt) * BKH);                     \
        cp16(&Bs[bufi][bRow][bCol8],      Bptr0 + (long long)(kt) * BKH * N);      \
        cp16(&Bs[bufi][bRow + 16][bCol8], Bptr1 + (long long)(kt) * BKH * N);      \
        asm volatile("cp.async.commit_group;");                                    \
    } while (0)

    LOAD_STAGE(0, 0);

    for (int kt = 0; kt < nTiles; kt++) {
        const int buf = kt & 1;
        const bool hasNext = (kt + 1 < nTiles);
        if (hasNext) LOAD_STAGE(buf ^ 1, kt + 1);

        if (hasNext) asm volatile("cp.async.wait_group 1;");
        else         asm volatile("cp.async.wait_group 0;");
        __syncthreads();

        // Two k16 steps
#pragma unroll
        for (int ks = 0; ks < 2; ks++) {
            const int k0 = ks * 16;
            unsigned af[2][4];
#pragma unroll
            for (int mt = 0; mt < 2; mt++) {
                const int r  = warpM * 32 + mt * 16 + (lane & 15);
                const int cc = k0 + (lane >> 4) * 8;
                ldsm_x4(af[mt][0], af[mt][1], af[mt][2], af[mt][3], &As[buf][r][cc]);
            }
            unsigned bf[4][4];
#pragma unroll
            for (int nb = 0; nb < 4; nb++) {
                const int rr = k0 + (lane & 15);
                const int cc = warpN * 64 + nb * 16 + (lane >> 4) * 8;
                ldsm_x4_t(bf[nb][0], bf[nb][1], bf[nb][2], bf[nb][3], &Bs[buf][rr][cc]);
            }
#pragma unroll
            for (int mt = 0; mt < 2; mt++)
#pragma unroll
                for (int nt = 0; nt < 8; nt++) {
                    float* d = acc[mt][nt];
                    const unsigned b0 = bf[nt >> 1][(nt & 1) * 2];
                    const unsigned b1 = bf[nt >> 1][(nt & 1) * 2 + 1];
                    asm volatile(
                        "mma.sync.aligned.m16n8k16.row.col.f32.f16.f16.f32 "
                        "{%0,%1,%2,%3}, {%4,%5,%6,%7}, {%8,%9}, {%0,%1,%2,%3};\n"
                        : "+f"(d[0]), "+f"(d[1]), "+f"(d[2]), "+f"(d[3])
                        : "r"(af[mt][0]), "r"(af[mt][1]), "r"(af[mt][2]), "r"(af[mt][3]),
                          "r"(b0), "r"(b1));
                }
        }
        __syncthreads();   // protect buf before next iteration overwrites it
    }

    // Epilogue: bias + store
#pragma unroll
    for (int nt = 0; nt < 8; nt++) {
        const int col = blockN + warpN * 64 + nt * 8 + 2 * c;
        const float bv0 = bias[col];
        const float bv1 = bias[col + 1];
#pragma unroll
        for (int mt = 0; mt < 2; mt++) {
            const long long row0 = blockM + warpM * 32 + mt * 16 + g;
            const float c00 = acc[mt][nt][0] + bv0;
            const float c01 = acc[mt][nt][1] + bv1;
            const float c10 = acc[mt][nt][2] + bv0;
            const float c11 = acc[mt][nt][3] + bv1;
            if (OUT_HALF) {
                __half* C = (__half*)Cout;
                *(__half2*)&C[row0 * N + col]       = __floats2half2_rn(c00, c01);
                *(__half2*)&C[(row0 + 8) * N + col] = __floats2half2_rn(c10, c11);
            } else {
                float* C = (float*)Cout;
                float2 v0 = { c00, c01 };
                float2 v1 = { c10, c11 };
                *(float2*)&C[row0 * N + col]       = v0;
                *(float2*)&C[(row0 + 8) * N + col] = v1;
            }
        }
    }
}

// ---------------------------------------------------------------------------
// Fused window attention: block = (window, head), 128 threads (4 warps).
// fp16 in (qkv), fp32 compute, fp16 out (att).
// ---------------------------------------------------------------------------
__global__ __launch_bounds__(128) void attn_kernel(
    const __half* __restrict__ qkv,
    const float* __restrict__ bias_table,
    __half* __restrict__ out)
{
    __shared__ float qs[NTOK][HDIM + 1];
    __shared__ float ks[NTOK][HDIM + 1];
    __shared__ float vs[NTOK][HDIM + 1];
    __shared__ float P[NTOK][NTOK + 3];
    __shared__ float bt[169];

    const int b    = blockIdx.x;
    const int h    = blockIdx.y;
    const int tid  = threadIdx.x;
    const int lane = tid & 31;
    const int warp = tid >> 5;
    const float scale = 0.17677669529663687f;  // 32^-0.5

    for (int idx = tid; idx < 169; idx += 128) bt[idx] = bias_table[idx * HEADS + h];

    // Stage q,k,v as half2 pairs: 49*16 = 784 pairs
    for (int p = tid; p < NTOK * (HDIM / 2); p += 128) {
        const int n = p >> 4;
        const int d = (p & 15) * 2;
        const size_t base = ((size_t)(b * NTOK + n)) * QKVCOL + h * HDIM + d;
        float2 q2 = __half22float2(*(const __half2*)&qkv[base]);
        float2 k2 = __half22float2(*(const __half2*)&qkv[base + CDIM]);
        float2 v2 = __half22float2(*(const __half2*)&qkv[base + 2 * CDIM]);
        qs[n][d] = q2.x * scale;  qs[n][d + 1] = q2.y * scale;
        ks[n][d] = k2.x;          ks[n][d + 1] = k2.y;
        vs[n][d] = v2.x;          vs[n][d + 1] = v2.y;
    }
    __syncthreads();

    // Scores + softmax: warp per row, cols split lane / lane+32
    const int j1 = lane + 32;
    const int rj0 = lane / 7,  cj0 = lane - rj0 * 7;
    const int rj1 = j1 / 7,    cj1 = j1 - rj1 * 7;
    for (int i = warp; i < NTOK; i += 4) {
        const int ri = i / 7, ci = i - ri * 7;
        float s0 = bt[(ri - rj0 + 6) * 13 + (ci - cj0 + 6)];
#pragma unroll
        for (int d = 0; d < HDIM; d++) s0 = fmaf(qs[i][d], ks[lane][d], s0);
        float s1 = -FLT_MAX;
        if (j1 < NTOK) {
            s1 = bt[(ri - rj1 + 6) * 13 + (ci - cj1 + 6)];
#pragma unroll
            for (int d = 0; d < HDIM; d++) s1 = fmaf(qs[i][d], ks[j1][d], s1);
        }
        float m = fmaxf(s0, s1);
#pragma unroll
        for (int off = 16; off >= 1; off >>= 1)
            m = fmaxf(m, __shfl_xor_sync(0xffffffffu, m, off));
        const float e0 = __expf(s0 - m);
        const float e1 = (j1 < NTOK) ? __expf(s1 - m) : 0.0f;
        float s = e0 + e1;
#pragma unroll
        for (int off = 16; off >= 1; off >>= 1)
            s += __shfl_xor_sync(0xffffffffu, s, off);
        const float inv = 1.0f / s;
        P[i][lane] = e0 * inv;
        if (j1 < NTOK) P[i][j1] = e1 * inv;
    }
    __syncthreads();

    // O = P @ V, write fp16 pairs
    for (int p = tid; p < NTOK * (HDIM / 2); p += 128) {
        const int i = p >> 4;
        const int d = (p & 15) * 2;
        float a0 = 0.0f, a1 = 0.0f;
#pragma unroll 7
        for (int j = 0; j < NTOK; j++) {
            a0 = fmaf(P[i][j], vs[j][d], a0);
            a1 = fmaf(P[i][j], vs[j][d + 1], a1);
        }
        const size_t o = ((size_t)(b * NTOK + i)) * CDIM + h * HDIM + d;
        *(__half2*)&out[o] = __floats2half2_rn(a0, a1);
    }
}

// ---------------------------------------------------------------------------
extern "C" void kernel_launch(void* const* d_in, const int* in_sizes, int n_in,
                              void* d_out, int out_size)
{
    const float* x          = (const float*)d_in[0];
    const float* w_qkv      = (const float*)d_in[1];
    const float* b_qkv      = (const float*)d_in[2];
    const float* w_proj     = (const float*)d_in[3];
    const float* b_proj     = (const float*)d_in[4];
    const float* bias_table = (const float*)d_in[5];
    float* out = (float*)d_out;

    __half *xh, *wqkvh, *wprojh, *qkvh, *atth;
    cudaGetSymbolAddress((void**)&xh,     g_xh);
    cudaGetSymbolAddress((void**)&wqkvh,  g_wqkvh);
    cudaGetSymbolAddress((void**)&wprojh, g_wprojh);
    cudaGetSymbolAddress((void**)&qkvh,   g_qkvh);
    cudaGetSymbolAddress((void**)&atth,   g_atth);

    // 0) fp32 -> fp16 conversions
    {
        const int n4x = MROWS * CDIM / 4;         // 19267584
        f32_to_f16<<<(n4x + 255) / 256, 256>>>(x, xh, n4x);
        const int n4q = CDIM * QKVCOL / 4;        // 110592
        f32_to_f16<<<(n4q + 255) / 256, 256>>>(w_qkv, wqkvh, n4q);
        const int n4p = CDIM * CDIM / 4;          // 36864
        f32_to_f16<<<(n4p + 255) / 256, 256>>>(w_proj, wprojh, n4p);
    }
    // 1) QKV = x @ w_qkv + b_qkv   (fp16 out)
    {
        dim3 grid(QKVCOL / BN, MROWS / BM);  // (9, 1568)
        gemm_f16<true><<<grid, 256>>>(xh, wqkvh, b_qkv, qkvh, MROWS, QKVCOL, CDIM);
    }
    // 2) Windowed attention (fp16 in/out)
    {
        dim3 grid(NWIN, HEADS);  // (4096, 12)
        attn_kernel<<<grid, 128>>>(qkvh, bias_table, atth);
    }
    // 3) out = att @ w_proj + b_proj   (fp32 out)
    {
        dim3 grid(CDIM / BN, MROWS / BM);  // (3, 1568)
        gemm_f16<false><<<grid, 256>>>(atth, wprojh, b_proj, out, MROWS, CDIM, CDIM);
    }
}